// round 14
// baseline (speedup 1.0000x reference)
#include <cuda_runtime.h>
#include <math.h>

// ---------------------------------------------------------------------------
// Problem constants
// ---------------------------------------------------------------------------
#define NB 4
#define SS 4096
#define DD 1024
#define HH 16
#define HD 64
#define FF 4096
#define TT (NB*SS)      // 16384 tokens

// ---------------------------------------------------------------------------
// Scratch (device globals; no allocations allowed)
// ---------------------------------------------------------------------------
__device__ float g_x[(size_t)TT*DD];     // x after LN1 (FFN input / residual)
__device__ float g_q[(size_t)TT*DD];
__device__ float g_k[(size_t)TT*DD];
__device__ float g_v[(size_t)TT*DD];
__device__ float g_a[(size_t)TT*DD];     // attention output
__device__ float g_t[(size_t)TT*DD];     // pre-LN sum buffer
__device__ float g_h[(size_t)TT*FF];     // FFN hidden
__device__ float g_kvt[NB*HH*HD*HD];     // KV^T per head: [nh][d][m]
__device__ float g_ksum[NB*HH*HD];
__device__ int   g_vlen[NB];

enum { EPI_NONE = 0, EPI_Q = 1, EPI_K = 2, EPI_GELU = 3, EPI_RES = 4 };

// ---------------------------------------------------------------------------
// valid length per batch (LengthMask semantics: S - count(padding))
// ---------------------------------------------------------------------------
__global__ void vlen_kernel(const unsigned char* __restrict__ mask) {
    int n = blockIdx.x;
    __shared__ int sh[256];
    int cnt = 0;
    for (int s = threadIdx.x; s < SS; s += 256) cnt += (mask[(size_t)n*SS + s] != 0);
    sh[threadIdx.x] = cnt;
    __syncthreads();
    for (int o = 128; o > 0; o >>= 1) {
        if (threadIdx.x < o) sh[threadIdx.x] += sh[threadIdx.x + o];
        __syncthreads();
    }
    if (threadIdx.x == 0) g_vlen[n] = SS - sh[0];
}

// ---------------------------------------------------------------------------
// fp32 NT GEMM: C[M,N] = A[M,K] @ B[N,K]^T + bias, fused epilogue.
// 128x128 block tile, BK=16, 256 threads, 8x8 per-thread microtile.
// M, N multiples of 128; K multiple of 16. Rows map to tokens (n = row>>12).
// ---------------------------------------------------------------------------
__global__ __launch_bounds__(256, 2)
void gemm_nt(const float* __restrict__ A, const float* __restrict__ B,
             const float* __restrict__ bias, const float* __restrict__ resid,
             float* __restrict__ C, int M, int N, int K, int epi)
{
    __shared__ float As[16][128];
    __shared__ float Bs[16][128];

    const int tid = threadIdx.x;
    const int rowBase = blockIdx.y * 128;
    const int colBase = blockIdx.x * 128;
    const float* Ab = A + (size_t)rowBase * K;
    const float* Bb = B + (size_t)colBase * K;

    float acc[8][8];
#pragma unroll
    for (int i = 0; i < 8; i++)
#pragma unroll
        for (int j = 0; j < 8; j++) acc[i][j] = 0.f;

    const int tr = (tid >> 4) * 8;
    const int tc = (tid & 15) * 8;

    for (int k0 = 0; k0 < K; k0 += 16) {
#pragma unroll
        for (int l = 0; l < 2; l++) {
            int li = tid + l * 256;            // 512 float4 per tile
            int r  = li >> 2;
            int c  = (li & 3) * 4;
            float4 fa = *(const float4*)(Ab + (size_t)r * K + k0 + c);
            As[c + 0][r] = fa.x; As[c + 1][r] = fa.y;
            As[c + 2][r] = fa.z; As[c + 3][r] = fa.w;
            float4 fb = *(const float4*)(Bb + (size_t)r * K + k0 + c);
            Bs[c + 0][r] = fb.x; Bs[c + 1][r] = fb.y;
            Bs[c + 2][r] = fb.z; Bs[c + 3][r] = fb.w;
        }
        __syncthreads();

#pragma unroll
        for (int kk = 0; kk < 16; kk++) {
            float ar[8], br[8];
            *(float4*)(ar)     = *(const float4*)&As[kk][tr];
            *(float4*)(ar + 4) = *(const float4*)&As[kk][tr + 4];
            *(float4*)(br)     = *(const float4*)&Bs[kk][tc];
            *(float4*)(br + 4) = *(const float4*)&Bs[kk][tc + 4];
#pragma unroll
            for (int i = 0; i < 8; i++)
#pragma unroll
                for (int j = 0; j < 8; j++) acc[i][j] += ar[i] * br[j];
        }
        __syncthreads();
    }

    // epilogue
#pragma unroll
    for (int i = 0; i < 8; i++) {
        int row  = rowBase + tr + i;
        int sIdx = row & (SS - 1);
        int nIdx = row >> 12;
        float fm = 1.f;
        if (epi == EPI_K) fm = (sIdx < g_vlen[nIdx]) ? 1.f : 0.f;
#pragma unroll
        for (int jj = 0; jj < 8; jj += 4) {
            float4 o;
            float* op = &o.x;
#pragma unroll
            for (int j = 0; j < 4; j++) {
                int col = colBase + tc + jj + j;
                float v = acc[i][jj + j] + bias[col];
                if (epi == EPI_Q || epi == EPI_K) {
                    v = (v > 0.f ? v + 1.f : __expf(v)) * fm;   // elu(v)+1
                } else if (epi == EPI_GELU) {
                    v = 0.5f * v * (1.f + erff(v * 0.70710678118654752f));
                } else if (epi == EPI_RES) {
                    v += resid[(size_t)row * N + col];
                }
                op[j] = v;
            }
            *(float4*)(C + (size_t)row * N + colBase + tc + jj) = o;
        }
    }
}

// ---------------------------------------------------------------------------
// KV^T + Ksum per (n,h): KV[m][d] = sum_s K[s][d]*V[s][m]; store as [d][m].
// 64 blocks (one per head-batch), 256 threads, 4x4 per thread.
// ---------------------------------------------------------------------------
__global__ __launch_bounds__(256, 1)
void kv_kernel(const float* __restrict__ Kf, const float* __restrict__ Vf)
{
    __shared__ float Ks[32][64];
    __shared__ float Vs[32][64];

    const int nh = blockIdx.x;
    const int n = nh >> 4, h = nh & 15;
    const int tid = threadIdx.x;
    const int tm = tid >> 4, tn = tid & 15;
    const int m0 = tm * 4, d0 = tn * 4;

    float acc[4][4] = {};
    float ks[4] = {};

    const float* Kb = Kf + ((size_t)n * SS) * DD + h * HD;
    const float* Vb = Vf + ((size_t)n * SS) * DD + h * HD;

    for (int s0 = 0; s0 < SS; s0 += 32) {
#pragma unroll
        for (int l = 0; l < 2; l++) {
            int li = tid + l * 256;            // 512 float4 = 32 rows x 16
            int r  = li >> 4;
            int c  = (li & 15) * 4;
            *(float4*)&Ks[r][c] = *(const float4*)(Kb + (size_t)(s0 + r) * DD + c);
            *(float4*)&Vs[r][c] = *(const float4*)(Vb + (size_t)(s0 + r) * DD + c);
        }
        __syncthreads();
#pragma unroll 8
        for (int ss = 0; ss < 32; ss++) {
            float kd[4], vm[4];
            *(float4*)kd = *(const float4*)&Ks[ss][d0];
            *(float4*)vm = *(const float4*)&Vs[ss][m0];
#pragma unroll
            for (int mi = 0; mi < 4; mi++)
#pragma unroll
                for (int di = 0; di < 4; di++) acc[mi][di] += vm[mi] * kd[di];
            if (tm == 0) {
                ks[0] += kd[0]; ks[1] += kd[1]; ks[2] += kd[2]; ks[3] += kd[3];
            }
        }
        __syncthreads();
    }

    float* kvb = g_kvt + (size_t)nh * HD * HD;
#pragma unroll
    for (int mi = 0; mi < 4; mi++)
#pragma unroll
        for (int di = 0; di < 4; di++)
            kvb[(d0 + di) * HD + (m0 + mi)] = acc[mi][di];
    if (tm == 0)
#pragma unroll
        for (int di = 0; di < 4; di++) g_ksum[nh * HD + d0 + di] = ks[di];
}

// ---------------------------------------------------------------------------
// attn[l][m] = z * sum_d Q[l][d] * KV^T[d][m],  z = 1/(Q.Ksum + eps)
// grid (64 head-batches, 64 token-chunks of 64), 256 threads = 8 warps,
// one warp per token, KV^T staged in smem (conflict-free: lane indexes m).
// ---------------------------------------------------------------------------
__global__ __launch_bounds__(256, 1)
void attn_kernel(const float* __restrict__ Qf, float* __restrict__ Af)
{
    __shared__ float KVs[64 * 64];
    __shared__ float ksm[64];
    __shared__ float Qs[8][64];

    const int nh = blockIdx.x;
    const int n = nh >> 4, h = nh & 15;
    const int tBase = blockIdx.y * 64;
    const int tid = threadIdx.x, lane = tid & 31, w = tid >> 5;

    const float* kvb = g_kvt + (size_t)nh * 4096;
    for (int i = tid; i < 1024; i += 256)
        *(float4*)&KVs[i * 4] = *(const float4*)&kvb[i * 4];
    if (tid < 64) ksm[tid] = g_ksum[nh * 64 + tid];
    __syncthreads();

    const float* Qb = Qf + ((size_t)n * SS) * DD + h * HD;
    float* Ab = Af + ((size_t)n * SS) * DD + h * HD;

    for (int g = 0; g < 8; g++) {
        int t0 = tBase + g * 8;
        if (tid < 128) {
            int r = tid >> 4, c = (tid & 15) * 4;
            *(float4*)&Qs[r][c] = *(const float4*)(Qb + (size_t)(t0 + r) * DD + c);
        }
        __syncthreads();

        float p = Qs[w][lane] * ksm[lane] + Qs[w][lane + 32] * ksm[lane + 32];
#pragma unroll
        for (int o = 16; o; o >>= 1) p += __shfl_xor_sync(0xffffffffu, p, o);
        float z = 1.f / (p + 1e-6f);

        float a0 = 0.f, a1 = 0.f;
#pragma unroll
        for (int d = 0; d < 64; d++) {
            float qd = Qs[w][d];
            a0 += qd * KVs[d * 64 + lane];
            a1 += qd * KVs[d * 64 + lane + 32];
        }
        float* op = Ab + (size_t)(t0 + w) * DD;
        op[lane]      = a0 * z;
        op[lane + 32] = a1 * z;
        __syncthreads();
    }
}

// ---------------------------------------------------------------------------
// LayerNorm over D=1024 (one block per row, 256 threads, float4 per thread)
// ---------------------------------------------------------------------------
__global__ __launch_bounds__(256, 4)
void ln_kernel(const float* __restrict__ X, const float* __restrict__ G,
               const float* __restrict__ B, float* __restrict__ Y)
{
    __shared__ float s1[8], s2[8];
    const int row = blockIdx.x, tid = threadIdx.x;
    const int lane = tid & 31, w = tid >> 5;

    float4 x = ((const float4*)(X + (size_t)row * DD))[tid];
    float s = x.x + x.y + x.z + x.w;
    float q = x.x*x.x + x.y*x.y + x.z*x.z + x.w*x.w;
#pragma unroll
    for (int o = 16; o; o >>= 1) {
        s += __shfl_xor_sync(0xffffffffu, s, o);
        q += __shfl_xor_sync(0xffffffffu, q, o);
    }
    if (lane == 0) { s1[w] = s; s2[w] = q; }
    __syncthreads();
    float st = 0.f, qt = 0.f;
#pragma unroll
    for (int i = 0; i < 8; i++) { st += s1[i]; qt += s2[i]; }

    float mu  = st * (1.f / DD);
    float var = qt * (1.f / DD) - mu * mu;
    float rs  = rsqrtf(var + 1e-5f);

    float4 g = ((const float4*)G)[tid];
    float4 b = ((const float4*)B)[tid];
    float4 o;
    o.x = (x.x - mu) * rs * g.x + b.x;
    o.y = (x.y - mu) * rs * g.y + b.y;
    o.z = (x.z - mu) * rs * g.z + b.z;
    o.w = (x.w - mu) * rs * g.w + b.w;
    ((float4*)(Y + (size_t)row * DD))[tid] = o;
}

// ---------------------------------------------------------------------------
// launch
// ---------------------------------------------------------------------------
extern "C" void kernel_launch(void* const* d_in, const int* in_sizes, int n_in,
                              void* d_out, int out_size)
{
    (void)in_sizes; (void)n_in; (void)out_size;

    const float* src = (const float*)d_in[0];
    const unsigned char* mask = (const unsigned char*)d_in[1];
    const float* Wq = (const float*)d_in[2];
    const float* bq = (const float*)d_in[3];
    const float* Wk = (const float*)d_in[4];
    const float* bk = (const float*)d_in[5];
    const float* Wv = (const float*)d_in[6];
    const float* bv = (const float*)d_in[7];
    const float* Wo = (const float*)d_in[8];
    const float* bo = (const float*)d_in[9];
    const float* W1 = (const float*)d_in[10];
    const float* b1 = (const float*)d_in[11];
    const float* W2 = (const float*)d_in[12];
    const float* b2 = (const float*)d_in[13];
    const float* g1 = (const float*)d_in[14];
    const float* be1 = (const float*)d_in[15];
    const float* g2 = (const float*)d_in[16];
    const float* be2 = (const float*)d_in[17];

    float *x, *q, *k, *v, *a, *t, *h;
    cudaGetSymbolAddress((void**)&x, g_x);
    cudaGetSymbolAddress((void**)&q, g_q);
    cudaGetSymbolAddress((void**)&k, g_k);
    cudaGetSymbolAddress((void**)&v, g_v);
    cudaGetSymbolAddress((void**)&a, g_a);
    cudaGetSymbolAddress((void**)&t, g_t);
    cudaGetSymbolAddress((void**)&h, g_h);

    vlen_kernel<<<NB, 256>>>(mask);

    const dim3 gD(DD / 128, TT / 128);   // 8 x 128 blocks
    const dim3 gF(FF / 128, TT / 128);   // 32 x 128 blocks

    const float* xc = src;
    for (int i = 0; i < 4; i++) {
        const size_t wD = (size_t)i * DD * DD;
        const size_t wF = (size_t)i * FF * DD;

        gemm_nt<<<gD, 256>>>(xc, Wq + wD, bq + i * DD, nullptr, q, TT, DD, DD, EPI_Q);
        gemm_nt<<<gD, 256>>>(xc, Wk + wD, bk + i * DD, nullptr, k, TT, DD, DD, EPI_K);
        gemm_nt<<<gD, 256>>>(xc, Wv + wD, bv + i * DD, nullptr, v, TT, DD, DD, EPI_NONE);

        kv_kernel<<<NB * HH, 256>>>(k, v);
        attn_kernel<<<dim3(NB * HH, SS / 64), 256>>>(q, a);

        gemm_nt<<<gD, 256>>>(a, Wo + wD, bo + i * DD, xc, t, TT, DD, DD, EPI_RES);
        ln_kernel<<<TT, 256>>>(t, g1 + i * DD, be1 + i * DD, x);

        gemm_nt<<<gF, 256>>>(x, W1 + wF, b1 + i * FF, nullptr, h, TT, FF, DD, EPI_GELU);
        gemm_nt<<<gD, 256>>>(h, W2 + wF, b2 + i * DD, x, t, TT, DD, FF, EPI_RES);
        ln_kernel<<<TT, 256>>>(t, g2 + i * DD, be2 + i * DD,
                               (i == 3) ? (float*)d_out : x);
        xc = x;
    }
}

// round 16
// speedup vs baseline: 2.4766x; 2.4766x over previous
#include <cuda_runtime.h>
#include <cuda_bf16.h>
#include <math.h>
#include <stdint.h>

// ---------------------------------------------------------------------------
// Problem constants
// ---------------------------------------------------------------------------
#define NB 4
#define SS 4096
#define DD 1024
#define HH 16
#define HD 64
#define FF 4096
#define TT (NB*SS)          // 16384 tokens
#define K3D (3*DD)          // split-K for D=1024 -> 3072
#define K3F (3*FF)          // split-K for F=4096 -> 12288

// ---------------------------------------------------------------------------
// Scratch (device globals; no allocations allowed)
// ---------------------------------------------------------------------------
__device__ float g_x[(size_t)TT*DD];
__device__ float g_t[(size_t)TT*DD];
__device__ float g_q[(size_t)TT*DD];
__device__ float g_k[(size_t)TT*DD];
__device__ float g_v[(size_t)TT*DD];
__device__ __nv_bfloat16 g_x3[(size_t)TT*K3D];     // split activations (A-form)
__device__ __nv_bfloat16 g_a3[(size_t)TT*K3D];     // split attention out
__device__ __nv_bfloat16 g_h3[(size_t)TT*K3F];     // split FFN hidden
__device__ __nv_bfloat16 g_Wq3[(size_t)4*DD*K3D];  // split weights (B-form)
__device__ __nv_bfloat16 g_Wk3[(size_t)4*DD*K3D];
__device__ __nv_bfloat16 g_Wv3[(size_t)4*DD*K3D];
__device__ __nv_bfloat16 g_Wo3[(size_t)4*DD*K3D];
__device__ __nv_bfloat16 g_W13[(size_t)4*FF*K3D];
__device__ __nv_bfloat16 g_W23[(size_t)4*DD*K3F];
__device__ float g_kvt[NB*HH*HD*HD];
__device__ float g_ksum[NB*HH*HD];
__device__ int   g_vlen[NB];

enum { OP_NONE = 0, OP_ELU = 1, OP_ELUMASK = 2, OP_GELU = 3, OP_RES = 4 };

// ---------------------------------------------------------------------------
// PTX helpers (compute_103-safe: cp.async + ldmatrix + mma.sync only)
// ---------------------------------------------------------------------------
__device__ __forceinline__ uint32_t smem_u32(const void* p) {
    uint32_t a;
    asm("{ .reg .u64 t; cvta.to.shared.u64 t, %1; cvt.u32.u64 %0, t; }"
        : "=r"(a) : "l"(p));
    return a;
}
__device__ __forceinline__ void cp16(uint32_t dst, const void* src) {
    asm volatile("cp.async.cg.shared.global [%0], [%1], 16;"
                 :: "r"(dst), "l"(src));
}
__device__ __forceinline__ void ldsm4(uint32_t* r, uint32_t addr) {
    asm volatile("ldmatrix.sync.aligned.m8n8.x4.shared.b16 {%0,%1,%2,%3}, [%4];"
                 : "=r"(r[0]), "=r"(r[1]), "=r"(r[2]), "=r"(r[3]) : "r"(addr));
}
__device__ __forceinline__ void mma16816(float* d, const uint32_t* a,
                                         const uint32_t* b) {
    asm volatile(
        "mma.sync.aligned.m16n8k16.row.col.f32.bf16.bf16.f32 "
        "{%0,%1,%2,%3}, {%4,%5,%6,%7}, {%8,%9}, {%0,%1,%2,%3};"
        : "+f"(d[0]), "+f"(d[1]), "+f"(d[2]), "+f"(d[3])
        : "r"(a[0]), "r"(a[1]), "r"(a[2]), "r"(a[3]), "r"(b[0]), "r"(b[1]));
}

// ---------------------------------------------------------------------------
// valid length per batch
// ---------------------------------------------------------------------------
__global__ void vlen_kernel(const unsigned char* __restrict__ mask) {
    int n = blockIdx.x;
    __shared__ int sh[256];
    int cnt = 0;
    for (int s = threadIdx.x; s < SS; s += 256) cnt += (mask[(size_t)n*SS + s] != 0);
    sh[threadIdx.x] = cnt;
    __syncthreads();
    for (int o = 128; o > 0; o >>= 1) {
        if (threadIdx.x < o) sh[threadIdx.x] += sh[threadIdx.x + o];
        __syncthreads();
    }
    if (threadIdx.x == 0) g_vlen[n] = SS - sh[0];
}

// ---------------------------------------------------------------------------
// float -> split-bf16 triples.
// A-form (left operand):  (hi, hi, lo);  B-form (right operand): (hi, lo, hi)
// dot over triples = ah*bh + ah*bl + al*bh  (missing al*bl ~ 2^-16 relative)
// ---------------------------------------------------------------------------
__global__ void cvtA_kernel(const float* __restrict__ in,
                            __nv_bfloat16* __restrict__ out, int n) {
    int i = blockIdx.x * 256 + threadIdx.x;
    if (i < n) {
        float v = in[i];
        __nv_bfloat16 h = __float2bfloat16(v);
        __nv_bfloat16 l = __float2bfloat16(v - __bfloat162float(h));
        out[3*(size_t)i] = h; out[3*(size_t)i+1] = h; out[3*(size_t)i+2] = l;
    }
}
__global__ void cvtB_kernel(const float* __restrict__ in,
                            __nv_bfloat16* __restrict__ out, int n) {
    int i = blockIdx.x * 256 + threadIdx.x;
    if (i < n) {
        float v = in[i];
        __nv_bfloat16 h = __float2bfloat16(v);
        __nv_bfloat16 l = __float2bfloat16(v - __bfloat162float(h));
        out[3*(size_t)i] = h; out[3*(size_t)i+1] = l; out[3*(size_t)i+2] = h;
    }
}

// ---------------------------------------------------------------------------
// bf16 tensor-core GEMM (mma.sync): C[M,N] = A3[M,K3] @ B3[N,K3]^T + epilogue
// CTA 128x128, K-chunk 64 bf16 (SW128 128B rows), 3-stage cp.async pipeline,
// 256 threads = 8 warps (4x2), warp tile 32x64, fp32 register accumulators.
// ---------------------------------------------------------------------------
#define STAGES 3
#define STAGE_BYTES 32768              // A 16KB + B 16KB
#define GEMM_SMEM (STAGES*STAGE_BYTES) // 98304

__device__ __forceinline__ uint32_t swz(uint32_t o) {
    return o ^ ((o >> 3) & 0x70);      // SW128: granule ^= (row & 7)
}

__global__ __launch_bounds__(256, 2)
void gemm_tc(const __nv_bfloat16* __restrict__ A3,
             const __nv_bfloat16* __restrict__ B3,
             const float* __restrict__ bias, const float* __restrict__ resid,
             float* __restrict__ Cf, __nv_bfloat16* __restrict__ Cs,
             int M, int N, int K3, int op)
{
    extern __shared__ __align__(1024) char smem[];
    const uint32_t sb = smem_u32(smem);
    const int tid = threadIdx.x;
    const int rowBase = blockIdx.y * 128;
    const int colBase = blockIdx.x * 128;

    // ---- gmem -> smem load pattern: 4 A granules + 4 B granules / thread ----
    const int r0 = tid >> 3, cg = tid & 7;          // r0: 0..31, cg: 0..7
    uint32_t offs[4];
#pragma unroll
    for (int it = 0; it < 4; ++it)
        offs[it] = swz((uint32_t)((r0 + 32*it) * 128 + cg * 16));
    const __nv_bfloat16* pa = A3 + (size_t)(rowBase + r0) * K3 + cg * 8;
    const __nv_bfloat16* pb = B3 + (size_t)(colBase + r0) * K3 + cg * 8;
    const size_t step = (size_t)32 * K3;
    const int nCh = K3 >> 6;

#define LOAD_CHUNK(j) do {                                                    \
        uint32_t u = sb + ((j) % 3) * STAGE_BYTES;                            \
        int k0 = (j) * 64;                                                    \
        _Pragma("unroll")                                                     \
        for (int it = 0; it < 4; ++it) {                                      \
            cp16(u + offs[it],         pa + it * step + k0);                  \
            cp16(u + 16384 + offs[it], pb + it * step + k0);                  \
        }                                                                     \
    } while (0)

    // prologue
    LOAD_CHUNK(0); asm volatile("cp.async.commit_group;");
    LOAD_CHUNK(1); asm volatile("cp.async.commit_group;");

    // ---- per-lane ldmatrix address components ----
    const int lane = tid & 31, wid = tid >> 5;
    const int warp_m = wid & 3, warp_n = wid >> 2;   // 4 x 2 warps
    const int j8 = lane >> 3, rr = lane & 7;

    uint32_t baseA[2], xA[2];
#pragma unroll
    for (int mi = 0; mi < 2; ++mi) {
        int rowA = warp_m * 32 + mi * 16 + (j8 & 1) * 8 + rr;
        baseA[mi] = rowA * 128; xA[mi] = rowA & 7;
    }
    uint32_t baseB[4], xB[4];
#pragma unroll
    for (int nb = 0; nb < 4; ++nb) {
        int rowB = warp_n * 64 + nb * 16 + (j8 >> 1) * 8 + rr;
        baseB[nb] = 16384 + rowB * 128; xB[nb] = rowB & 7;
    }
    const uint32_t kgA = (uint32_t)(j8 >> 1);   // A: k-granule offset
    const uint32_t kgB = (uint32_t)(j8 & 1);    // B: k-granule offset

    float acc[2][8][4];
#pragma unroll
    for (int mi = 0; mi < 2; ++mi)
#pragma unroll
        for (int f = 0; f < 8; ++f)
#pragma unroll
            for (int e = 0; e < 4; ++e) acc[mi][f][e] = 0.f;

    // ---- mainloop ----
    for (int i = 0; i < nCh; ++i) {
        asm volatile("cp.async.wait_group 1;");
        __syncthreads();
        if (i + 2 < nCh) LOAD_CHUNK(i + 2);
        asm volatile("cp.async.commit_group;");

        const uint32_t st = sb + (i % 3) * STAGE_BYTES;
#pragma unroll
        for (int ks = 0; ks < 4; ++ks) {
            uint32_t a[2][4], b[4][4];
#pragma unroll
            for (int mi = 0; mi < 2; ++mi)
                ldsm4(a[mi], st + baseA[mi] + ((((uint32_t)ks*2 + kgA) ^ xA[mi]) << 4));
#pragma unroll
            for (int nb = 0; nb < 4; ++nb)
                ldsm4(b[nb], st + baseB[nb] + ((((uint32_t)ks*2 + kgB) ^ xB[nb]) << 4));
#pragma unroll
            for (int mi = 0; mi < 2; ++mi)
#pragma unroll
                for (int nb = 0; nb < 4; ++nb) {
                    mma16816(acc[mi][nb*2+0], a[mi], &b[nb][0]);
                    mma16816(acc[mi][nb*2+1], a[mi], &b[nb][2]);
                }
        }
        __syncthreads();
    }

    // ---- epilogue ----
    const int rw = rowBase + warp_m * 32 + (lane >> 2);
    const int cw = colBase + warp_n * 64 + (lane & 3) * 2;

#pragma unroll
    for (int mi = 0; mi < 2; ++mi) {
#pragma unroll
        for (int rh = 0; rh < 2; ++rh) {
            const int row = rw + mi * 16 + rh * 8;
            float fm = 1.f;
            if (op == OP_ELUMASK)
                fm = ((row & (SS-1)) < g_vlen[row >> 12]) ? 1.f : 0.f;
#pragma unroll
            for (int f = 0; f < 8; ++f) {
                const int col = cw + f * 8;
                float v0 = acc[mi][f][rh*2+0] + __ldg(bias + col);
                float v1 = acc[mi][f][rh*2+1] + __ldg(bias + col + 1);
                if (op == OP_ELU || op == OP_ELUMASK) {
                    v0 = (v0 > 0.f ? v0 + 1.f : __expf(v0)) * fm;
                    v1 = (v1 > 0.f ? v1 + 1.f : __expf(v1)) * fm;
                } else if (op == OP_GELU) {
                    v0 = 0.5f * v0 * (1.f + erff(v0 * 0.70710678118654752f));
                    v1 = 0.5f * v1 * (1.f + erff(v1 * 0.70710678118654752f));
                } else if (op == OP_RES) {
                    float2 rv = *(const float2*)(resid + (size_t)row * N + col);
                    v0 += rv.x; v1 += rv.y;
                }
                if (Cf)
                    *(float2*)(Cf + (size_t)row * N + col) = make_float2(v0, v1);
                if (Cs) {
                    __nv_bfloat16* sp = Cs + ((size_t)row * N + col) * 3;
                    __nv_bfloat16 h0 = __float2bfloat16(v0);
                    __nv_bfloat16 l0 = __float2bfloat16(v0 - __bfloat162float(h0));
                    __nv_bfloat16 h1 = __float2bfloat16(v1);
                    __nv_bfloat16 l1 = __float2bfloat16(v1 - __bfloat162float(h1));
                    sp[0] = h0; sp[1] = h0; sp[2] = l0;
                    sp[3] = h1; sp[4] = h1; sp[5] = l1;
                }
            }
        }
    }
#undef LOAD_CHUNK
}

// ---------------------------------------------------------------------------
// KV^T + Ksum per (n,h)
// ---------------------------------------------------------------------------
__global__ __launch_bounds__(256, 1)
void kv_kernel(const float* __restrict__ Kf, const float* __restrict__ Vf)
{
    __shared__ float Ks[32][64];
    __shared__ float Vs[32][64];

    const int nh = blockIdx.x;
    const int n = nh >> 4, h = nh & 15;
    const int tid = threadIdx.x;
    const int tm = tid >> 4, tn = tid & 15;
    const int m0 = tm * 4, d0 = tn * 4;

    float acc[4][4] = {};
    float ks[4] = {};

    const float* Kb = Kf + ((size_t)n * SS) * DD + h * HD;
    const float* Vb = Vf + ((size_t)n * SS) * DD + h * HD;

    for (int s0 = 0; s0 < SS; s0 += 32) {
#pragma unroll
        for (int l = 0; l < 2; l++) {
            int li = tid + l * 256;
            int r  = li >> 4;
            int c  = (li & 15) * 4;
            *(float4*)&Ks[r][c] = *(const float4*)(Kb + (size_t)(s0 + r) * DD + c);
            *(float4*)&Vs[r][c] = *(const float4*)(Vb + (size_t)(s0 + r) * DD + c);
        }
        __syncthreads();
#pragma unroll 8
        for (int ss = 0; ss < 32; ss++) {
            float kd[4], vm[4];
            *(float4*)kd = *(const float4*)&Ks[ss][d0];
            *(float4*)vm = *(const float4*)&Vs[ss][m0];
#pragma unroll
            for (int mi = 0; mi < 4; mi++)
#pragma unroll
                for (int di = 0; di < 4; di++) acc[mi][di] += vm[mi] * kd[di];
            if (tm == 0) {
                ks[0] += kd[0]; ks[1] += kd[1]; ks[2] += kd[2]; ks[3] += kd[3];
            }
        }
        __syncthreads();
    }

    float* kvb = g_kvt + (size_t)nh * HD * HD;
#pragma unroll
    for (int mi = 0; mi < 4; mi++)
#pragma unroll
        for (int di = 0; di < 4; di++)
            kvb[(d0 + di) * HD + (m0 + mi)] = acc[mi][di];
    if (tm == 0)
#pragma unroll
        for (int di = 0; di < 4; di++) g_ksum[nh * HD + d0 + di] = ks[di];
}

// ---------------------------------------------------------------------------
// attn -> split-bf16 triples (A-form) directly into g_a3
// ---------------------------------------------------------------------------
__global__ __launch_bounds__(256, 1)
void attn_kernel(const float* __restrict__ Qf)
{
    __shared__ float KVs[64 * 64];
    __shared__ float ksm[64];
    __shared__ float Qs[8][64];

    const int nh = blockIdx.x;
    const int n = nh >> 4, h = nh & 15;
    const int tBase = blockIdx.y * 64;
    const int tid = threadIdx.x, lane = tid & 31, w = tid >> 5;

    const float* kvb = g_kvt + (size_t)nh * 4096;
    for (int i = tid; i < 1024; i += 256)
        *(float4*)&KVs[i * 4] = *(const float4*)&kvb[i * 4];
    if (tid < 64) ksm[tid] = g_ksum[nh * 64 + tid];
    __syncthreads();

    const float* Qb = Qf + ((size_t)n * SS) * DD + h * HD;

    for (int g = 0; g < 8; g++) {
        int t0 = tBase + g * 8;
        if (tid < 128) {
            int r = tid >> 4, c = (tid & 15) * 4;
            *(float4*)&Qs[r][c] = *(const float4*)(Qb + (size_t)(t0 + r) * DD + c);
        }
        __syncthreads();

        float p = Qs[w][lane] * ksm[lane] + Qs[w][lane + 32] * ksm[lane + 32];
#pragma unroll
        for (int o = 16; o; o >>= 1) p += __shfl_xor_sync(0xffffffffu, p, o);
        float z = 1.f / (p + 1e-6f);

        float a0 = 0.f, a1 = 0.f;
#pragma unroll
        for (int d = 0; d < 64; d++) {
            float qd = Qs[w][d];
            a0 += qd * KVs[d * 64 + lane];
            a1 += qd * KVs[d * 64 + lane + 32];
        }
        float v0 = a0 * z, v1 = a1 * z;
        __nv_bfloat16 h0 = __float2bfloat16(v0);
        __nv_bfloat16 l0 = __float2bfloat16(v0 - __bfloat162float(h0));
        __nv_bfloat16 h1 = __float2bfloat16(v1);
        __nv_bfloat16 l1 = __float2bfloat16(v1 - __bfloat162float(h1));
        __nv_bfloat16* op3 = g_a3 + (size_t)((size_t)n * SS + t0 + w) * K3D + h * HD * 3;
        op3[3*lane]        = h0; op3[3*lane+1]      = h0; op3[3*lane+2]      = l0;
        op3[3*(lane+32)]   = h1; op3[3*(lane+32)+1] = h1; op3[3*(lane+32)+2] = l1;
        __syncthreads();
    }
}

// ---------------------------------------------------------------------------
// LayerNorm over D=1024, optionally also emit split-bf16 triples (A-form)
// ---------------------------------------------------------------------------
__global__ __launch_bounds__(256, 4)
void ln_kernel(const float* __restrict__ X, const float* __restrict__ G,
               const float* __restrict__ B, float* __restrict__ Y,
               __nv_bfloat16* __restrict__ Y3)
{
    __shared__ float s1[8], s2[8];
    const int row = blockIdx.x, tid = threadIdx.x;
    const int lane = tid & 31, w = tid >> 5;

    float4 x = ((const float4*)(X + (size_t)row * DD))[tid];
    float s = x.x + x.y + x.z + x.w;
    float q = x.x*x.x + x.y*x.y + x.z*x.z + x.w*x.w;
#pragma unroll
    for (int o = 16; o; o >>= 1) {
        s += __shfl_xor_sync(0xffffffffu, s, o);
        q += __shfl_xor_sync(0xffffffffu, q, o);
    }
    if (lane == 0) { s1[w] = s; s2[w] = q; }
    __syncthreads();
    float st = 0.f, qt = 0.f;
#pragma unroll
    for (int i = 0; i < 8; i++) { st += s1[i]; qt += s2[i]; }

    float mu  = st * (1.f / DD);
    float var = qt * (1.f / DD) - mu * mu;
    float rs  = rsqrtf(var + 1e-5f);

    float4 g = ((const float4*)G)[tid];
    float4 b = ((const float4*)B)[tid];
    float4 o;
    o.x = (x.x - mu) * rs * g.x + b.x;
    o.y = (x.y - mu) * rs * g.y + b.y;
    o.z = (x.z - mu) * rs * g.z + b.z;
    o.w = (x.w - mu) * rs * g.w + b.w;
    ((float4*)(Y + (size_t)row * DD))[tid] = o;

    if (Y3) {
        __nv_bfloat16* p = Y3 + (size_t)row * K3D + tid * 12;
        const float* ov = &o.x;
#pragma unroll
        for (int e = 0; e < 4; e++) {
            float v = ov[e];
            __nv_bfloat16 h = __float2bfloat16(v);
            __nv_bfloat16 l = __float2bfloat16(v - __bfloat162float(h));
            p[3*e] = h; p[3*e+1] = h; p[3*e+2] = l;
        }
    }
}

// ---------------------------------------------------------------------------
// launch
// ---------------------------------------------------------------------------
extern "C" void kernel_launch(void* const* d_in, const int* in_sizes, int n_in,
                              void* d_out, int out_size)
{
    (void)in_sizes; (void)n_in; (void)out_size;

    const float* src = (const float*)d_in[0];
    const unsigned char* mask = (const unsigned char*)d_in[1];
    const float* Wq = (const float*)d_in[2];
    const float* bq = (const float*)d_in[3];
    const float* Wk = (const float*)d_in[4];
    const float* bk = (const float*)d_in[5];
    const float* Wv = (const float*)d_in[6];
    const float* bv = (const float*)d_in[7];
    const float* Wo = (const float*)d_in[8];
    const float* bo = (const float*)d_in[9];
    const float* W1 = (const float*)d_in[10];
    const float* b1 = (const float*)d_in[11];
    const float* W2 = (const float*)d_in[12];
    const float* b2 = (const float*)d_in[13];
    const float* g1 = (const float*)d_in[14];
    const float* be1 = (const float*)d_in[15];
    const float* g2 = (const float*)d_in[16];
    const float* be2 = (const float*)d_in[17];

    float *x, *t, *q, *k, *v;
    __nv_bfloat16 *x3, *a3, *h3, *Wq3, *Wk3, *Wv3, *Wo3, *W13, *W23;
    cudaGetSymbolAddress((void**)&x, g_x);
    cudaGetSymbolAddress((void**)&t, g_t);
    cudaGetSymbolAddress((void**)&q, g_q);
    cudaGetSymbolAddress((void**)&k, g_k);
    cudaGetSymbolAddress((void**)&v, g_v);
    cudaGetSymbolAddress((void**)&x3, g_x3);
    cudaGetSymbolAddress((void**)&a3, g_a3);
    cudaGetSymbolAddress((void**)&h3, g_h3);
    cudaGetSymbolAddress((void**)&Wq3, g_Wq3);
    cudaGetSymbolAddress((void**)&Wk3, g_Wk3);
    cudaGetSymbolAddress((void**)&Wv3, g_Wv3);
    cudaGetSymbolAddress((void**)&Wo3, g_Wo3);
    cudaGetSymbolAddress((void**)&W13, g_W13);
    cudaGetSymbolAddress((void**)&W23, g_W23);

    cudaFuncSetAttribute(gemm_tc, cudaFuncAttributeMaxDynamicSharedMemorySize,
                         GEMM_SMEM);

    vlen_kernel<<<NB, 256>>>(mask);

    // weight split conversions
    cvtB_kernel<<<(4*DD*DD + 255)/256, 256>>>(Wq, Wq3, 4*DD*DD);
    cvtB_kernel<<<(4*DD*DD + 255)/256, 256>>>(Wk, Wk3, 4*DD*DD);
    cvtB_kernel<<<(4*DD*DD + 255)/256, 256>>>(Wv, Wv3, 4*DD*DD);
    cvtB_kernel<<<(4*DD*DD + 255)/256, 256>>>(Wo, Wo3, 4*DD*DD);
    cvtB_kernel<<<(4*FF*DD + 255)/256, 256>>>(W1, W13, 4*FF*DD);
    cvtB_kernel<<<(4*DD*FF + 255)/256, 256>>>(W2, W23, 4*DD*FF);

    // initial activation split
    cvtA_kernel<<<(TT*DD + 255)/256, 256>>>(src, x3, TT*DD);

    const dim3 gD(DD / 128, TT / 128);   // 8 x 128
    const dim3 gF(FF / 128, TT / 128);   // 32 x 128

    const float* xc = src;
    for (int i = 0; i < 4; i++) {
        const size_t wD = (size_t)i * DD * K3D;
        const size_t wF1 = (size_t)i * FF * K3D;
        const size_t wF2 = (size_t)i * DD * K3F;

        gemm_tc<<<gD, 256, GEMM_SMEM>>>(x3, Wq3 + wD, bq + i*DD, nullptr,
                                        q, nullptr, TT, DD, K3D, OP_ELU);
        gemm_tc<<<gD, 256, GEMM_SMEM>>>(x3, Wk3 + wD, bk + i*DD, nullptr,
                                        k, nullptr, TT, DD, K3D, OP_ELUMASK);
        gemm_tc<<<gD, 256, GEMM_SMEM>>>(x3, Wv3 + wD, bv + i*DD, nullptr,
                                        v, nullptr, TT, DD, K3D, OP_NONE);

        kv_kernel<<<NB * HH, 256>>>(k, v);
        attn_kernel<<<dim3(NB * HH, SS / 64), 256>>>(q);

        gemm_tc<<<gD, 256, GEMM_SMEM>>>(a3, Wo3 + wD, bo + i*DD, xc,
                                        t, nullptr, TT, DD, K3D, OP_RES);
        ln_kernel<<<TT, 256>>>(t, g1 + i*DD, be1 + i*DD, x, x3);

        gemm_tc<<<gF, 256, GEMM_SMEM>>>(x3, W13 + wF1, b1 + i*FF, nullptr,
                                        nullptr, h3, TT, FF, K3D, OP_GELU);
        gemm_tc<<<gD, 256, GEMM_SMEM>>>(h3, W23 + wF2, b2 + i*DD, x,
                                        t, nullptr, TT, DD, K3F, OP_RES);
        ln_kernel<<<TT, 256>>>(t, g2 + i*DD, be2 + i*DD,
                               (i == 3) ? (float*)d_out : x,
                               (i == 3) ? nullptr : x3);
        xc = x;
    }
}

// round 17
// speedup vs baseline: 3.2824x; 1.3253x over previous
#include <cuda_runtime.h>
#include <cuda_bf16.h>
#include <math.h>
#include <stdint.h>

// ---------------------------------------------------------------------------
// Problem constants
// ---------------------------------------------------------------------------
#define NB 4
#define SS 4096
#define DD 1024
#define HH 16
#define HD 64
#define FF 4096
#define TT (NB*SS)          // 16384 tokens
#define K2D (2*DD)          // plane-packed K for D=1024 -> 2048
#define K2F (2*FF)          // plane-packed K for F=4096 -> 8192
#define KVSPLIT 8

// ---------------------------------------------------------------------------
// Scratch (device globals; no allocations allowed)
// ---------------------------------------------------------------------------
__device__ float g_x[(size_t)TT*DD];
__device__ float g_t[(size_t)TT*DD];
__device__ float g_q[(size_t)TT*DD];
__device__ float g_k[(size_t)TT*DD];
__device__ float g_v[(size_t)TT*DD];
__device__ __nv_bfloat16 g_x3[(size_t)TT*K2D];     // plane-packed activations
__device__ __nv_bfloat16 g_a3[(size_t)TT*K2D];     // plane-packed attention out
__device__ __nv_bfloat16 g_h3[(size_t)TT*K2F];     // plane-packed FFN hidden
__device__ __nv_bfloat16 g_Wq3[(size_t)4*DD*K2D];  // plane-packed weights
__device__ __nv_bfloat16 g_Wk3[(size_t)4*DD*K2D];
__device__ __nv_bfloat16 g_Wv3[(size_t)4*DD*K2D];
__device__ __nv_bfloat16 g_Wo3[(size_t)4*DD*K2D];
__device__ __nv_bfloat16 g_W13[(size_t)4*FF*K2D];
__device__ __nv_bfloat16 g_W23[(size_t)4*DD*K2F];
__device__ float g_kvp[(size_t)KVSPLIT*NB*HH*(HD*HD+HD)];  // partial KV+ksum
__device__ float g_kvt[NB*HH*HD*HD];
__device__ float g_ksum[NB*HH*HD];
__device__ int   g_vlen[NB];

enum { OP_NONE = 0, OP_ELU = 1, OP_ELUMASK = 2, OP_GELU = 3, OP_RES = 4 };

// ---------------------------------------------------------------------------
// PTX helpers (compute_103-safe: cp.async + ldmatrix + mma.sync only)
// ---------------------------------------------------------------------------
__device__ __forceinline__ uint32_t smem_u32(const void* p) {
    uint32_t a;
    asm("{ .reg .u64 t; cvta.to.shared.u64 t, %1; cvt.u32.u64 %0, t; }"
        : "=r"(a) : "l"(p));
    return a;
}
__device__ __forceinline__ void cp16(uint32_t dst, const void* src) {
    asm volatile("cp.async.cg.shared.global [%0], [%1], 16;"
                 :: "r"(dst), "l"(src));
}
__device__ __forceinline__ void ldsm4(uint32_t* r, uint32_t addr) {
    asm volatile("ldmatrix.sync.aligned.m8n8.x4.shared.b16 {%0,%1,%2,%3}, [%4];"
                 : "=r"(r[0]), "=r"(r[1]), "=r"(r[2]), "=r"(r[3]) : "r"(addr));
}
__device__ __forceinline__ void mma16816(float* d, const uint32_t* a,
                                         const uint32_t* b) {
    asm volatile(
        "mma.sync.aligned.m16n8k16.row.col.f32.bf16.bf16.f32 "
        "{%0,%1,%2,%3}, {%4,%5,%6,%7}, {%8,%9}, {%0,%1,%2,%3};"
        : "+f"(d[0]), "+f"(d[1]), "+f"(d[2]), "+f"(d[3])
        : "r"(a[0]), "r"(a[1]), "r"(a[2]), "r"(a[3]), "r"(b[0]), "r"(b[1]));
}

// ---------------------------------------------------------------------------
// valid length per batch
// ---------------------------------------------------------------------------
__global__ void vlen_kernel(const unsigned char* __restrict__ mask) {
    int n = blockIdx.x;
    __shared__ int sh[256];
    int cnt = 0;
    for (int s = threadIdx.x; s < SS; s += 256) cnt += (mask[(size_t)n*SS + s] != 0);
    sh[threadIdx.x] = cnt;
    __syncthreads();
    for (int o = 128; o > 0; o >>= 1) {
        if (threadIdx.x < o) sh[threadIdx.x] += sh[threadIdx.x + o];
        __syncthreads();
    }
    if (threadIdx.x == 0) g_vlen[n] = SS - sh[0];
}

// ---------------------------------------------------------------------------
// float -> plane-packed split bf16.
// Row layout (per 32 original k): [hi k0..k31 | lo k0..k31]  (64B + 64B)
// Row stride = 2K elements. dot = ah*bh + ah*bl + al*bh (missing al*bl ~2^-16)
// ---------------------------------------------------------------------------
__global__ void cvt_kernel(const float* __restrict__ in,
                           __nv_bfloat16* __restrict__ out,
                           int logK, int n) {
    int i = blockIdx.x * 256 + threadIdx.x;
    if (i < n) {
        int K = 1 << logK;
        int row = i >> logK, k = i & (K - 1);
        float v = in[i];
        __nv_bfloat16 h = __float2bfloat16(v);
        __nv_bfloat16 l = __float2bfloat16(v - __bfloat162float(h));
        size_t base = (size_t)row * (K << 1) + ((k >> 5) << 6) + (k & 31);
        out[base] = h; out[base + 32] = l;
    }
}

// ---------------------------------------------------------------------------
// bf16 tensor-core GEMM (mma.sync): C[M,N] = A@B^T via split planes + epilogue
// CTA 128x128, chunk = 32 original k (hi+lo = 128B smem rows), 3-stage
// cp.async pipeline, 256 threads = 8 warps (4x2), warp tile 32x64, fp32 acc.
// ---------------------------------------------------------------------------
#define STAGES 3
#define STAGE_BYTES 32768              // A 16KB + B 16KB
#define GEMM_SMEM (STAGES*STAGE_BYTES) // 98304

__device__ __forceinline__ uint32_t swz(uint32_t o) {
    return o ^ ((o >> 3) & 0x70);      // 16B granule ^= (row & 7)
}

__global__ __launch_bounds__(256, 2)
void gemm_tc(const __nv_bfloat16* __restrict__ A2,
             const __nv_bfloat16* __restrict__ B2,
             const float* __restrict__ bias, const float* __restrict__ resid,
             float* __restrict__ Cf, __nv_bfloat16* __restrict__ Cs,
             int M, int N, int K2, int op)
{
    extern __shared__ __align__(1024) char smem[];
    const uint32_t sb = smem_u32(smem);
    const int tid = threadIdx.x;
    const int rowBase = blockIdx.y * 128;
    const int colBase = blockIdx.x * 128;

    // ---- gmem -> smem: 4 A granules + 4 B granules / thread / chunk ----
    const int r0 = tid >> 3, cg = tid & 7;
    uint32_t offs[4];
#pragma unroll
    for (int it = 0; it < 4; ++it)
        offs[it] = swz((uint32_t)((r0 + 32*it) * 128 + cg * 16));
    const __nv_bfloat16* pa = A2 + (size_t)(rowBase + r0) * K2 + cg * 8;
    const __nv_bfloat16* pb = B2 + (size_t)(colBase + r0) * K2 + cg * 8;
    const size_t step = (size_t)32 * K2;
    const int nCh = K2 >> 6;

#define LOAD_CHUNK(j) do {                                                    \
        uint32_t u = sb + ((j) % 3) * STAGE_BYTES;                            \
        int k0 = (j) * 64;                                                    \
        _Pragma("unroll")                                                     \
        for (int it = 0; it < 4; ++it) {                                      \
            cp16(u + offs[it],         pa + it * step + k0);                  \
            cp16(u + 16384 + offs[it], pb + it * step + k0);                  \
        }                                                                     \
    } while (0)

    LOAD_CHUNK(0); asm volatile("cp.async.commit_group;");
    LOAD_CHUNK(1); asm volatile("cp.async.commit_group;");

    // ---- per-lane ldmatrix address components ----
    const int lane = tid & 31, wid = tid >> 5;
    const int warp_m = wid & 3, warp_n = wid >> 2;   // 4 x 2 warps
    const int j8 = lane >> 3, rr = lane & 7;

    uint32_t baseA[2], xA[2];
#pragma unroll
    for (int mi = 0; mi < 2; ++mi) {
        int rowA = warp_m * 32 + mi * 16 + (j8 & 1) * 8 + rr;
        baseA[mi] = rowA * 128; xA[mi] = rowA & 7;
    }
    uint32_t baseB[4], xB[4];
#pragma unroll
    for (int nb = 0; nb < 4; ++nb) {
        int rowB = warp_n * 64 + nb * 16 + (j8 >> 1) * 8 + rr;
        baseB[nb] = 16384 + rowB * 128; xB[nb] = rowB & 7;
    }
    const uint32_t kgA = (uint32_t)(j8 >> 1);
    const uint32_t kgB = (uint32_t)(j8 & 1);

    float acc[2][8][4];
#pragma unroll
    for (int mi = 0; mi < 2; ++mi)
#pragma unroll
        for (int f = 0; f < 8; ++f)
#pragma unroll
            for (int e = 0; e < 4; ++e) acc[mi][f][e] = 0.f;

    // ---- mainloop: per chunk 2 k16-steps; per step hi/lo planes ----
    for (int i = 0; i < nCh; ++i) {
        asm volatile("cp.async.wait_group 1;");
        __syncthreads();
        if (i + 2 < nCh) LOAD_CHUNK(i + 2);
        asm volatile("cp.async.commit_group;");

        const uint32_t st = sb + (i % 3) * STAGE_BYTES;
#pragma unroll
        for (int ks = 0; ks < 2; ++ks) {
            uint32_t ah[2][4], al[2][4];
#pragma unroll
            for (int mi = 0; mi < 2; ++mi) {
                ldsm4(ah[mi], st + baseA[mi] + ((((uint32_t)(ks*2) + kgA) ^ xA[mi]) << 4));
                ldsm4(al[mi], st + baseA[mi] + ((((uint32_t)(4 + ks*2) + kgA) ^ xA[mi]) << 4));
            }
#pragma unroll
            for (int nb = 0; nb < 4; ++nb) {
                uint32_t bh[4], bl[4];
                ldsm4(bh, st + baseB[nb] + ((((uint32_t)(ks*2) + kgB) ^ xB[nb]) << 4));
                ldsm4(bl, st + baseB[nb] + ((((uint32_t)(4 + ks*2) + kgB) ^ xB[nb]) << 4));
#pragma unroll
                for (int mi = 0; mi < 2; ++mi) {
                    mma16816(acc[mi][nb*2+0], ah[mi], &bh[0]);
                    mma16816(acc[mi][nb*2+1], ah[mi], &bh[2]);
                    mma16816(acc[mi][nb*2+0], al[mi], &bh[0]);
                    mma16816(acc[mi][nb*2+1], al[mi], &bh[2]);
                    mma16816(acc[mi][nb*2+0], ah[mi], &bl[0]);
                    mma16816(acc[mi][nb*2+1], ah[mi], &bl[2]);
                }
            }
        }
        __syncthreads();
    }

    // ---- epilogue ----
    const int rw = rowBase + warp_m * 32 + (lane >> 2);
    const int cw = colBase + warp_n * 64 + (lane & 3) * 2;

#pragma unroll
    for (int mi = 0; mi < 2; ++mi) {
#pragma unroll
        for (int rh = 0; rh < 2; ++rh) {
            const int row = rw + mi * 16 + rh * 8;
            float fm = 1.f;
            if (op == OP_ELUMASK)
                fm = ((row & (SS-1)) < g_vlen[row >> 12]) ? 1.f : 0.f;
#pragma unroll
            for (int f = 0; f < 8; ++f) {
                const int col = cw + f * 8;
                float v0 = acc[mi][f][rh*2+0] + __ldg(bias + col);
                float v1 = acc[mi][f][rh*2+1] + __ldg(bias + col + 1);
                if (op == OP_ELU || op == OP_ELUMASK) {
                    v0 = (v0 > 0.f ? v0 + 1.f : __expf(v0)) * fm;
                    v1 = (v1 > 0.f ? v1 + 1.f : __expf(v1)) * fm;
                } else if (op == OP_GELU) {
                    v0 = 0.5f * v0 * (1.f + erff(v0 * 0.70710678118654752f));
                    v1 = 0.5f * v1 * (1.f + erff(v1 * 0.70710678118654752f));
                } else if (op == OP_RES) {
                    float2 rv = *(const float2*)(resid + (size_t)row * N + col);
                    v0 += rv.x; v1 += rv.y;
                }
                if (Cf)
                    *(float2*)(Cf + (size_t)row * N + col) = make_float2(v0, v1);
                if (Cs) {
                    // plane-packed: hi at group*64 + (c&31), lo at +32
                    __nv_bfloat16* sp = Cs + (size_t)row * 2 * N
                                      + ((size_t)(col >> 5) << 6) + (col & 31);
                    __nv_bfloat16 h0 = __float2bfloat16(v0);
                    __nv_bfloat16 l0 = __float2bfloat16(v0 - __bfloat162float(h0));
                    __nv_bfloat16 h1 = __float2bfloat16(v1);
                    __nv_bfloat16 l1 = __float2bfloat16(v1 - __bfloat162float(h1));
                    *(__nv_bfloat162*)(sp)      = __nv_bfloat162(h0, h1);
                    *(__nv_bfloat162*)(sp + 32) = __nv_bfloat162(l0, l1);
                }
            }
        }
    }
#undef LOAD_CHUNK
}

// ---------------------------------------------------------------------------
// Partial KV^T + Ksum: grid (64 heads, KVSPLIT s-chunks)
// ---------------------------------------------------------------------------
__global__ __launch_bounds__(256, 1)
void kv_part(const float* __restrict__ Kf, const float* __restrict__ Vf)
{
    __shared__ float Ks[32][64];
    __shared__ float Vs[32][64];

    const int nh = blockIdx.x;
    const int part = blockIdx.y;
    const int n = nh >> 4, h = nh & 15;
    const int tid = threadIdx.x;
    const int tm = tid >> 4, tn = tid & 15;
    const int m0 = tm * 4, d0 = tn * 4;
    const int sBeg = part * (SS / KVSPLIT), sEnd = sBeg + (SS / KVSPLIT);

    float acc[4][4] = {};
    float ks[4] = {};

    const float* Kb = Kf + ((size_t)n * SS) * DD + h * HD;
    const float* Vb = Vf + ((size_t)n * SS) * DD + h * HD;

    for (int s0 = sBeg; s0 < sEnd; s0 += 32) {
#pragma unroll
        for (int l = 0; l < 2; l++) {
            int li = tid + l * 256;
            int r  = li >> 4;
            int c  = (li & 15) * 4;
            *(float4*)&Ks[r][c] = *(const float4*)(Kb + (size_t)(s0 + r) * DD + c);
            *(float4*)&Vs[r][c] = *(const float4*)(Vb + (size_t)(s0 + r) * DD + c);
        }
        __syncthreads();
#pragma unroll 8
        for (int ss = 0; ss < 32; ss++) {
            float kd[4], vm[4];
            *(float4*)kd = *(const float4*)&Ks[ss][d0];
            *(float4*)vm = *(const float4*)&Vs[ss][m0];
#pragma unroll
            for (int mi = 0; mi < 4; mi++)
#pragma unroll
                for (int di = 0; di < 4; di++) acc[mi][di] += vm[mi] * kd[di];
            if (tm == 0) {
                ks[0] += kd[0]; ks[1] += kd[1]; ks[2] += kd[2]; ks[3] += kd[3];
            }
        }
        __syncthreads();
    }

    float* kvb = g_kvp + ((size_t)part * 64 + nh) * (HD*HD + HD);
#pragma unroll
    for (int mi = 0; mi < 4; mi++)
#pragma unroll
        for (int di = 0; di < 4; di++)
            kvb[(d0 + di) * HD + (m0 + mi)] = acc[mi][di];
    if (tm == 0)
#pragma unroll
        for (int di = 0; di < 4; di++) kvb[HD*HD + d0 + di] = ks[di];
}

__global__ void kv_reduce() {
    const int nh = blockIdx.x, tid = threadIdx.x;
    for (int i = tid; i < HD*HD + HD; i += 256) {
        float s = 0.f;
#pragma unroll
        for (int p = 0; p < KVSPLIT; ++p)
            s += g_kvp[((size_t)p * 64 + nh) * (HD*HD + HD) + i];
        if (i < HD*HD) g_kvt[nh * HD*HD + i] = s;
        else           g_ksum[nh * HD + (i - HD*HD)] = s;
    }
}

// ---------------------------------------------------------------------------
// attn -> plane-packed split bf16 directly into g_a3
// ---------------------------------------------------------------------------
__global__ __launch_bounds__(256, 1)
void attn_kernel(const float* __restrict__ Qf)
{
    __shared__ float KVs[64 * 64];
    __shared__ float ksm[64];
    __shared__ float Qs[8][64];

    const int nh = blockIdx.x;
    const int n = nh >> 4, h = nh & 15;
    const int tBase = blockIdx.y * 64;
    const int tid = threadIdx.x, lane = tid & 31, w = tid >> 5;

    const float* kvb = g_kvt + (size_t)nh * 4096;
    for (int i = tid; i < 1024; i += 256)
        *(float4*)&KVs[i * 4] = *(const float4*)&kvb[i * 4];
    if (tid < 64) ksm[tid] = g_ksum[nh * 64 + tid];
    __syncthreads();

    const float* Qb = Qf + ((size_t)n * SS) * DD + h * HD;

    for (int g = 0; g < 8; g++) {
        int t0 = tBase + g * 8;
        if (tid < 128) {
            int r = tid >> 4, c = (tid & 15) * 4;
            *(float4*)&Qs[r][c] = *(const float4*)(Qb + (size_t)(t0 + r) * DD + c);
        }
        __syncthreads();

        float p = Qs[w][lane] * ksm[lane] + Qs[w][lane + 32] * ksm[lane + 32];
#pragma unroll
        for (int o = 16; o; o >>= 1) p += __shfl_xor_sync(0xffffffffu, p, o);
        float z = 1.f / (p + 1e-6f);

        float a0 = 0.f, a1 = 0.f;
#pragma unroll
        for (int d = 0; d < 64; d++) {
            float qd = Qs[w][d];
            a0 += qd * KVs[d * 64 + lane];
            a1 += qd * KVs[d * 64 + lane + 32];
        }
        float v0 = a0 * z, v1 = a1 * z;
        __nv_bfloat16 h0 = __float2bfloat16(v0);
        __nv_bfloat16 l0 = __float2bfloat16(v0 - __bfloat162float(h0));
        __nv_bfloat16 h1 = __float2bfloat16(v1);
        __nv_bfloat16 l1 = __float2bfloat16(v1 - __bfloat162float(h1));
        // cols c0 = h*64+lane (group h*2), c1 = h*64+32+lane (group h*2+1)
        __nv_bfloat16* rp = g_a3 + (size_t)((size_t)n * SS + t0 + w) * K2D;
        rp[(h*2)   * 64 + lane]      = h0;
        rp[(h*2)   * 64 + lane + 32] = l0;
        rp[(h*2+1) * 64 + lane]      = h1;
        rp[(h*2+1) * 64 + lane + 32] = l1;
        __syncthreads();
    }
}

// ---------------------------------------------------------------------------
// LayerNorm over D=1024, optionally emit plane-packed split bf16
// ---------------------------------------------------------------------------
__global__ __launch_bounds__(256, 4)
void ln_kernel(const float* __restrict__ X, const float* __restrict__ G,
               const float* __restrict__ B, float* __restrict__ Y,
               __nv_bfloat16* __restrict__ Y3)
{
    __shared__ float s1[8], s2[8];
    const int row = blockIdx.x, tid = threadIdx.x;
    const int lane = tid & 31, w = tid >> 5;

    float4 x = ((const float4*)(X + (size_t)row * DD))[tid];
    float s = x.x + x.y + x.z + x.w;
    float q = x.x*x.x + x.y*x.y + x.z*x.z + x.w*x.w;
#pragma unroll
    for (int o = 16; o; o >>= 1) {
        s += __shfl_xor_sync(0xffffffffu, s, o);
        q += __shfl_xor_sync(0xffffffffu, q, o);
    }
    if (lane == 0) { s1[w] = s; s2[w] = q; }
    __syncthreads();
    float st = 0.f, qt = 0.f;
#pragma unroll
    for (int i = 0; i < 8; i++) { st += s1[i]; qt += s2[i]; }

    float mu  = st * (1.f / DD);
    float var = qt * (1.f / DD) - mu * mu;
    float rs  = rsqrtf(var + 1e-5f);

    float4 g = ((const float4*)G)[tid];
    float4 b = ((const float4*)B)[tid];
    float4 o;
    o.x = (x.x - mu) * rs * g.x + b.x;
    o.y = (x.y - mu) * rs * g.y + b.y;
    o.z = (x.z - mu) * rs * g.z + b.z;
    o.w = (x.w - mu) * rs * g.w + b.w;
    ((float4*)(Y + (size_t)row * DD))[tid] = o;

    if (Y3) {
        const int c = tid * 4;                       // 4 contiguous cols, same group
        __nv_bfloat16* p = Y3 + (size_t)row * K2D + ((c >> 5) << 6) + (c & 31);
        const float* ov = &o.x;
#pragma unroll
        for (int e = 0; e < 4; e++) {
            float v = ov[e];
            __nv_bfloat16 h = __float2bfloat16(v);
            __nv_bfloat16 l = __float2bfloat16(v - __bfloat162float(h));
            p[e] = h; p[e + 32] = l;
        }
    }
}

// ---------------------------------------------------------------------------
// launch
// ---------------------------------------------------------------------------
extern "C" void kernel_launch(void* const* d_in, const int* in_sizes, int n_in,
                              void* d_out, int out_size)
{
    (void)in_sizes; (void)n_in; (void)out_size;

    const float* src = (const float*)d_in[0];
    const unsigned char* mask = (const unsigned char*)d_in[1];
    const float* Wq = (const float*)d_in[2];
    const float* bq = (const float*)d_in[3];
    const float* Wk = (const float*)d_in[4];
    const float* bk = (const float*)d_in[5];
    const float* Wv = (const float*)d_in[6];
    const float* bv = (const float*)d_in[7];
    const float* Wo = (const float*)d_in[8];
    const float* bo = (const float*)d_in[9];
    const float* W1 = (const float*)d_in[10];
    const float* b1 = (const float*)d_in[11];
    const float* W2 = (const float*)d_in[12];
    const float* b2 = (const float*)d_in[13];
    const float* g1 = (const float*)d_in[14];
    const float* be1 = (const float*)d_in[15];
    const float* g2 = (const float*)d_in[16];
    const float* be2 = (const float*)d_in[17];

    float *x, *t, *q, *k, *v;
    __nv_bfloat16 *x3, *a3, *h3, *Wq3, *Wk3, *Wv3, *Wo3, *W13, *W23;
    cudaGetSymbolAddress((void**)&x, g_x);
    cudaGetSymbolAddress((void**)&t, g_t);
    cudaGetSymbolAddress((void**)&q, g_q);
    cudaGetSymbolAddress((void**)&k, g_k);
    cudaGetSymbolAddress((void**)&v, g_v);
    cudaGetSymbolAddress((void**)&x3, g_x3);
    cudaGetSymbolAddress((void**)&a3, g_a3);
    cudaGetSymbolAddress((void**)&h3, g_h3);
    cudaGetSymbolAddress((void**)&Wq3, g_Wq3);
    cudaGetSymbolAddress((void**)&Wk3, g_Wk3);
    cudaGetSymbolAddress((void**)&Wv3, g_Wv3);
    cudaGetSymbolAddress((void**)&Wo3, g_Wo3);
    cudaGetSymbolAddress((void**)&W13, g_W13);
    cudaGetSymbolAddress((void**)&W23, g_W23);

    cudaFuncSetAttribute(gemm_tc, cudaFuncAttributeMaxDynamicSharedMemorySize,
                         GEMM_SMEM);

    vlen_kernel<<<NB, 256>>>(mask);

    // weight conversions (plane-packed; K = D for all but W2 which has K = F)
    cvt_kernel<<<(4*DD*DD + 255)/256, 256>>>(Wq, Wq3, 10, 4*DD*DD);
    cvt_kernel<<<(4*DD*DD + 255)/256, 256>>>(Wk, Wk3, 10, 4*DD*DD);
    cvt_kernel<<<(4*DD*DD + 255)/256, 256>>>(Wv, Wv3, 10, 4*DD*DD);
    cvt_kernel<<<(4*DD*DD + 255)/256, 256>>>(Wo, Wo3, 10, 4*DD*DD);
    cvt_kernel<<<(4*FF*DD + 255)/256, 256>>>(W1, W13, 10, 4*FF*DD);
    cvt_kernel<<<(4*DD*FF + 255)/256, 256>>>(W2, W23, 12, 4*DD*FF);

    // initial activation conversion
    cvt_kernel<<<(TT*DD + 255)/256, 256>>>(src, x3, 10, TT*DD);

    const dim3 gD(DD / 128, TT / 128);   // 8 x 128
    const dim3 gF(FF / 128, TT / 128);   // 32 x 128

    const float* xc = src;
    for (int i = 0; i < 4; i++) {
        const size_t wD  = (size_t)i * DD * K2D;
        const size_t wF1 = (size_t)i * FF * K2D;
        const size_t wF2 = (size_t)i * DD * K2F;

        gemm_tc<<<gD, 256, GEMM_SMEM>>>(x3, Wq3 + wD, bq + i*DD, nullptr,
                                        q, nullptr, TT, DD, K2D, OP_ELU);
        gemm_tc<<<gD, 256, GEMM_SMEM>>>(x3, Wk3 + wD, bk + i*DD, nullptr,
                                        k, nullptr, TT, DD, K2D, OP_ELUMASK);
        gemm_tc<<<gD, 256, GEMM_SMEM>>>(x3, Wv3 + wD, bv + i*DD, nullptr,
                                        v, nullptr, TT, DD, K2D, OP_NONE);

        kv_part<<<dim3(NB * HH, KVSPLIT), 256>>>(k, v);
        kv_reduce<<<NB * HH, 256>>>();
        attn_kernel<<<dim3(NB * HH, SS / 64), 256>>>(q);

        gemm_tc<<<gD, 256, GEMM_SMEM>>>(a3, Wo3 + wD, bo + i*DD, xc,
                                        t, nullptr, TT, DD, K2D, OP_RES);
        ln_kernel<<<TT, 256>>>(t, g1 + i*DD, be1 + i*DD, x, x3);

        gemm_tc<<<gF, 256, GEMM_SMEM>>>(x3, W13 + wF1, b1 + i*FF, nullptr,
                                        nullptr, h3, TT, FF, K2D, OP_GELU);
        gemm_tc<<<gD, 256, GEMM_SMEM>>>(h3, W23 + wF2, b2 + i*DD, x,
                                        t, nullptr, TT, DD, K2F, OP_RES);
        ln_kernel<<<TT, 256>>>(t, g2 + i*DD, be2 + i*DD,
                               (i == 3) ? (float*)d_out : x,
                               (i == 3) ? nullptr : x3);
        xc = x;
    }
}